// round 17
// baseline (speedup 1.0000x reference)
#include <cuda_runtime.h>
#include <cuda_bf16.h>
#include <stdint.h>
#include <math.h>
#include <mma.h>

using namespace nvcuda;

#define BB   128
#define TT   256
#define SS   64
#define IIN  3
#define HH   512
#define KK   10
#define CSL  60
#define OUTD 121
#define G4   2048
#define K1TOT 575
#define K2TOT 512
#define NBLK 128
#define K1PAD 576
#define WS1  584     // W smem row stride (rec1)
#define WS2  520     // W smem row stride (rec2)
#define APAD 40      // A smem tile row stride (32 b + 8 pad)
#define SLOTB 20480  // stage slot bytes: 128 rows x APAD x 2B x 2 ops

// ---------------- global scratch ------------------------------------------------
__device__ __nv_bfloat16 g_a1h[2][K1PAD*BB];
__device__ __nv_bfloat16 g_a1l[2][K1PAD*BB];
__device__ __nv_bfloat16 g_a2h[2][K2TOT*BB];
__device__ __nv_bfloat16 g_a2l[2][K2TOT*BB];
__device__ __nv_bfloat16 g_featT_h[(size_t)TT*K1PAD*BB];
__device__ __nv_bfloat16 g_featT_l[(size_t)TT*K1PAD*BB];
__device__ __nv_bfloat16 g_yT_h[(size_t)TT*K2TOT*BB];
__device__ __nv_bfloat16 g_yT_l[(size_t)TT*K2TOT*BB];
__device__ __nv_bfloat16 g_wl_h[(size_t)G4*K1PAD];
__device__ __nv_bfloat16 g_wl_l[(size_t)G4*K1PAD];
__device__ __nv_bfloat16 g_wo_h[128*K2TOT];
__device__ __nv_bfloat16 g_wo_l[128*K2TOT];
__device__ float g_l2inT[(size_t)TT*G4*BB];
__device__ float g_h1f[BB*HH], g_c1f[BB*HH], g_h2f[BB*HH], g_c2f[BB*HH];

// ---------------- grid barrier -------------------------------------------------
__device__ unsigned g_cnt = 0;
__device__ volatile unsigned g_gen = 0;

__device__ __forceinline__ void gbar()
{
    __syncthreads();
    if (threadIdx.x == 0){
        unsigned my = g_gen;
        __threadfence();
        if (atomicAdd(&g_cnt, 1u) == NBLK-1u){
            g_cnt = 0;
            __threadfence();
            g_gen = my + 1u;
        } else {
            while (g_gen == my) __nanosleep(32);
        }
        __threadfence();
    }
    __syncthreads();
}

__device__ __forceinline__ float sigf(float x){ return 1.0f/(1.0f+expf(-x)); }

__device__ __forceinline__ void bsplit(float v, __nv_bfloat16* hp, __nv_bfloat16* lp){
    __nv_bfloat16 h = __float2bfloat16(v);
    *hp = h;
    *lp = __float2bfloat16(v - __bfloat162float(h));
}

// ---------------- cp.async helpers --------------------------------------------
__device__ __forceinline__ void cpa16(void* dst, const void* src){
    unsigned d = (unsigned)__cvta_generic_to_shared(dst);
    asm volatile("cp.async.ca.shared.global [%0], [%1], 16;" :: "r"(d), "l"(src));
}
__device__ __forceinline__ void cpcommit(){ asm volatile("cp.async.commit_group;"); }
__device__ __forceinline__ void cpwait0(){ asm volatile("cp.async.wait_group 0;"); }
__device__ __forceinline__ void cpwait1(){ asm volatile("cp.async.wait_group 1;"); }

// ---------------- init ---------------------------------------------------------
__global__ void k_init(const float* __restrict__ h1h, const float* __restrict__ h2h)
{
    int i = blockIdx.x*blockDim.x + threadIdx.x;
    if (i < BB*HH){
        int b = i/HH, h = i%HH;
        bsplit(h1h[i], &g_a1h[0][(63+h)*BB+b], &g_a1l[0][(63+h)*BB+b]);
        bsplit(h2h[i], &g_a2h[0][h*BB+b],      &g_a2l[0][h*BB+b]);
    }
}

// ---------------- convert parallel-GEMM weights --------------------------------
__global__ void k_cvt_w(const float* __restrict__ Wihl, const float* __restrict__ W2)
{
    const int n1 = G4*K1TOT;
    const int n2 = OUTD*K2TOT;
    int total = n1 + n2;
    for (int i = blockIdx.x*blockDim.x + threadIdx.x; i < total; i += gridDim.x*blockDim.x){
        if (i < n1){
            int j = i / K1TOT, k = i % K1TOT;
            bsplit(Wihl[i], &g_wl_h[(size_t)j*K1PAD + k], &g_wl_l[(size_t)j*K1PAD + k]);
        } else {
            int i2 = i - n1;
            bsplit(W2[i2], &g_wo_h[i2], &g_wo_l[i2]);
        }
    }
}

// ================= persistent layer-1: HMMA + attention-overlapped ============
__global__ void __launch_bounds__(512,1)
k_rec1(const float* __restrict__ x,    const float* __restrict__ Wihc,
       const float* __restrict__ Whhc, const float* __restrict__ bc,
       const float* __restrict__ W1,   const float* __restrict__ b1,
       const float* __restrict__ sent, const float* __restrict__ h1c_in)
{
    extern __shared__ char smem[];
    __nv_bfloat16* Wh = (__nv_bfloat16*)smem;                    // 64 x WS1
    __nv_bfloat16* Wl = (__nv_bfloat16*)(smem + 74752);
    char*  Abase = smem + 149504;                                // 2 slots x 20480B
    float* Cs    = (float*)(smem + 149504);                      // alias, 16KB
    float* sentS = (float*)(smem + 190464);                      // 3840 f
    float* sh    = (float*)(smem + 205824);                      // 512 f
    float* sp    = (float*)(smem + 207872);                      // 32 f
    float* sphi  = (float*)(smem + 208000);                      // 64 f

    const int tid = threadIdx.x;
    const int blk = blockIdx.x;
    const int htile = blk >> 2, btile = blk & 3;
    const int batt  = blk;
    const int wrp  = tid >> 5;
    const int khalf = wrp >> 3, mi = (wrp >> 2) & 1, ni = wrp & 3;
    const int cl_h = tid >> 5, cl_b = tid & 31;
    const int hg = htile*16 + cl_h, bG = btile*32 + cl_b;

    for (int idx = tid; idx < 64*WS1; idx += 512){
        int n = idx / WS1, k = idx - n*WS1;
        float v = 0.f;
        if (k < K1TOT){
            int j = (n>>4)*512 + htile*16 + (n&15);
            v = (k < 63) ? Wihc[(size_t)j*63 + k] : Whhc[(size_t)j*512 + (k-63)];
        }
        bsplit(v, &Wh[idx], &Wl[idx]);
    }
    for (int idx = tid; idx < SS*CSL; idx += 512)
        sentS[idx] = sent[(size_t)batt*SS*CSL + idx];
    if (tid < 32) sp[tid] = 0.f;

    float c1r = h1c_in[(size_t)bG*HH + hg];
    const float bi0=bc[hg], bi1=bc[512+hg], bi2=bc[1024+hg], bi3=bc[1536+hg];
    __syncthreads();

    for (int t = 0; t < TT; t++){
        const int p = t & 1;
        const __nv_bfloat16* Ahg = g_a1h[p];
        const __nv_bfloat16* Alg = g_a1l[p];

        // h-chunk loader: 128 k-rows at k = 64 + ci*128
        auto load_h = [&](int slot, int ci){
            int op = tid >> 8, r = tid & 255;
            #pragma unroll
            for (int q = 0; q < 2; q++){
                int idx = r + q*256;
                int kk = idx >> 2, seg = idx & 3;
                const __nv_bfloat16* src = (op ? Alg : Ahg)
                    + (size_t)(64 + ci*128 + kk)*BB + btile*32 + seg*8;
                cpa16(Abase + slot*SLOTB + op*10240 + kk*(APAD*2) + seg*16, src);
            }
            cpcommit();
        };
        auto mma_slot = [&](int slot, int kgbase, int nsub,
                            wmma::fragment<wmma::accumulator,16,16,16,float>& acc){
            const __nv_bfloat16* Ast_h = (const __nv_bfloat16*)(Abase + slot*SLOTB);
            const __nv_bfloat16* Ast_l = (const __nv_bfloat16*)(Abase + slot*SLOTB + 10240);
            for (int s2 = 0; s2 < nsub; s2++){
                int koff = khalf*(nsub*16) + s2*16;
                int kg   = kgbase + koff;
                wmma::fragment<wmma::matrix_a,16,16,16,__nv_bfloat16,wmma::col_major> fah, fal;
                wmma::load_matrix_sync(fah, Ast_h + koff*APAD + mi*16, APAD);
                wmma::load_matrix_sync(fal, Ast_l + koff*APAD + mi*16, APAD);
                wmma::fragment<wmma::matrix_b,16,16,16,__nv_bfloat16,wmma::col_major> fbh, fbl;
                wmma::load_matrix_sync(fbh, Wh + (size_t)ni*16*WS1 + kg, WS1);
                wmma::load_matrix_sync(fbl, Wl + (size_t)ni*16*WS1 + kg, WS1);
                wmma::mma_sync(acc, fah, fbh, acc);
                wmma::mma_sync(acc, fah, fbl, acc);
                wmma::mma_sync(acc, fal, fbh, acc);
            }
        };

        // ---- phase: x writes + attention j-dots + h-part GEMM (overlapped) ---
        if (tid < IIN){
            float v = x[((size_t)batt*TT + t)*IIN + tid];
            bsplit(v, &g_a1h[p][tid*BB+batt], &g_a1l[p][tid*BB+batt]);
            size_t fo = (size_t)t*K1PAD*BB + tid*BB + batt;
            bsplit(v, &g_featT_h[fo], &g_featT_l[fo]);
        }
        sh[tid] = __bfloat162float(Ahg[(63+tid)*BB + batt])
                + __bfloat162float(Alg[(63+tid)*BB + batt]);
        __syncthreads();

        load_h(0, 0);
        load_h(1, 1);

        {   // attention ip = exp(h @ W1^T + b1); kappa subtracts previous
            int w2 = tid>>5, lane = tid&31;
            for (int j = w2; j < 30; j += 16){
                float s = 0.f;
                #pragma unroll 8
                for (int k = lane; k < 512; k += 32) s += sh[k]*W1[j*512+k];
                #pragma unroll
                for (int o=16;o;o>>=1) s += __shfl_down_sync(0xffffffffu, s, o);
                if (lane == 0){
                    float v = expf(s + b1[j]);
                    if (j >= 20) v -= sp[j];
                    sp[j] = v;
                }
            }
        }

        wmma::fragment<wmma::accumulator,16,16,16,float> acc;
        wmma::fill_fragment(acc, 0.f);

        for (int ci = 0; ci < 4; ci++){
            if (ci+1 < 4) cpwait1(); else cpwait0();
            __syncthreads();                      // also publishes sp (ci==0) / sphi (ci==1)
            mma_slot(ci&1, 64 + ci*128, 4, acc);
            if (ci == 0 && tid < SS){
                float u = (float)(tid+1), a = 0.f;
                #pragma unroll
                for (int k=0;k<KK;k++){
                    float d = sp[20+k] - u;
                    a += sp[k]*expf(-sp[10+k]*d*d);
                }
                sphi[tid] = a;
            }
            if (ci == 1 && tid < CSL){
                float a = 0.f;
                #pragma unroll 8
                for (int s=0;s<SS;s++) a += sphi[s]*sentS[s*CSL + tid];
                bsplit(a, &g_a1h[p][(3+tid)*BB+batt], &g_a1l[p][(3+tid)*BB+batt]);
                size_t fo = (size_t)t*K1PAD*BB + (3+tid)*BB + batt;
                bsplit(a, &g_featT_h[fo], &g_featT_l[fo]);
            }
            __syncthreads();
            if (ci+2 < 4) load_h(ci&1, ci+2);
        }

        gbar();                                   // win/x from all blocks now visible

        // chunk 0 (k 0..63: x | win | h[0]) into slot 0
        {
            int op = tid >> 8, r = tid & 255;
            int kk = r >> 2, seg = r & 3;
            const __nv_bfloat16* src = (op ? Alg : Ahg)
                + (size_t)kk*BB + btile*32 + seg*8;
            cpa16(Abase + op*10240 + kk*(APAD*2) + seg*16, src);
            cpcommit();
            cpwait0();
        }
        __syncthreads();
        mma_slot(0, 0, 2, acc);
        __syncthreads();
        wmma::store_matrix_sync(Cs + khalf*2048 + ni*16*32 + mi*16, acc, 32,
                                wmma::mem_col_major);
        __syncthreads();

        // fused cell
        float g0 = Cs[(0*16+cl_h)*32 + cl_b] + Cs[2048 + (0*16+cl_h)*32 + cl_b] + bi0;
        float g1 = Cs[(1*16+cl_h)*32 + cl_b] + Cs[2048 + (1*16+cl_h)*32 + cl_b] + bi1;
        float g2 = Cs[(2*16+cl_h)*32 + cl_b] + Cs[2048 + (2*16+cl_h)*32 + cl_b] + bi2;
        float g3 = Cs[(3*16+cl_h)*32 + cl_b] + Cs[2048 + (3*16+cl_h)*32 + cl_b] + bi3;
        float cn = sigf(g1)*c1r + sigf(g0)*tanhf(g2);
        float hn = sigf(g3)*tanhf(cn);
        c1r = cn;
        __nv_bfloat16 hhi, hlo;
        bsplit(hn, &hhi, &hlo);
        g_a1h[p^1][(63+hg)*BB + bG] = hhi;
        g_a1l[p^1][(63+hg)*BB + bG] = hlo;
        size_t fo = (size_t)t*K1PAD*BB + (63+hg)*BB + bG;
        g_featT_h[fo] = hhi;
        g_featT_l[fo] = hlo;
        if (t == TT-1){
            g_h1f[(size_t)bG*HH + hg] = hn;
            g_c1f[(size_t)bG*HH + hg] = cn;
        }
        gbar();
    }
}

// ================= persistent layer-2: HMMA recurrence ========================
__global__ void __launch_bounds__(512,1)
k_rec2(const float* __restrict__ Whhl, const float* __restrict__ h2c_in)
{
    extern __shared__ char smem[];
    __nv_bfloat16* Wh = (__nv_bfloat16*)smem;                    // 64 x WS2
    __nv_bfloat16* Wl = (__nv_bfloat16*)(smem + 66560);
    char*  Abase = smem + 133120;                                // 2 slots x 20480B
    float* Cs    = (float*)(smem + 133120);                      // alias, 16KB

    const int tid = threadIdx.x;
    const int blk = blockIdx.x;
    const int htile = blk >> 2, btile = blk & 3;
    const int wrp  = tid >> 5;
    const int khalf = wrp >> 3, mi = (wrp >> 2) & 1, ni = wrp & 3;
    const int cl_h = tid >> 5, cl_b = tid & 31;
    const int hg = htile*16 + cl_h, bG = btile*32 + cl_b;

    for (int idx = tid; idx < 64*WS2; idx += 512){
        int n = idx / WS2, k = idx - n*WS2;
        float v = 0.f;
        if (k < K2TOT){
            int j = (n>>4)*512 + htile*16 + (n&15);
            v = Whhl[(size_t)j*K2TOT + k];
        }
        bsplit(v, &Wh[idx], &Wl[idx]);
    }
    float c2r = h2c_in[(size_t)bG*HH + hg];
    __syncthreads();

    for (int t = 0; t < TT; t++){
        const int p = t & 1;
        const __nv_bfloat16* Ahg = g_a2h[p];
        const __nv_bfloat16* Alg = g_a2l[p];

        auto load_h = [&](int slot, int ci){
            int op = tid >> 8, r = tid & 255;
            #pragma unroll
            for (int q = 0; q < 2; q++){
                int idx = r + q*256;
                int kk = idx >> 2, seg = idx & 3;
                const __nv_bfloat16* src = (op ? Alg : Ahg)
                    + (size_t)(ci*128 + kk)*BB + btile*32 + seg*8;
                cpa16(Abase + slot*SLOTB + op*10240 + kk*(APAD*2) + seg*16, src);
            }
            cpcommit();
        };

        // hoist gate loads: L2 latency overlaps the GEMM below
        const float* li = g_l2inT + (size_t)t*G4*BB;
        float li0 = li[(size_t)(hg       )*BB + bG];
        float li1 = li[(size_t)(hg +  512)*BB + bG];
        float li2 = li[(size_t)(hg + 1024)*BB + bG];
        float li3 = li[(size_t)(hg + 1536)*BB + bG];

        load_h(0, 0);
        load_h(1, 1);

        wmma::fragment<wmma::accumulator,16,16,16,float> acc;
        wmma::fill_fragment(acc, 0.f);

        for (int ci = 0; ci < 4; ci++){
            if (ci+1 < 4) cpwait1(); else cpwait0();
            __syncthreads();
            const __nv_bfloat16* Ast_h = (const __nv_bfloat16*)(Abase + (ci&1)*SLOTB);
            const __nv_bfloat16* Ast_l = (const __nv_bfloat16*)(Abase + (ci&1)*SLOTB + 10240);
            #pragma unroll
            for (int s2 = 0; s2 < 4; s2++){
                int koff = khalf*64 + s2*16;
                int kg   = ci*128 + koff;
                wmma::fragment<wmma::matrix_a,16,16,16,__nv_bfloat16,wmma::col_major> fah, fal;
                wmma::load_matrix_sync(fah, Ast_h + koff*APAD + mi*16, APAD);
                wmma::load_matrix_sync(fal, Ast_l + koff*APAD + mi*16, APAD);
                wmma::fragment<wmma::matrix_b,16,16,16,__nv_bfloat16,wmma::col_major> fbh, fbl;
                wmma::load_matrix_sync(fbh, Wh + (size_t)ni*16*WS2 + kg, WS2);
                wmma::load_matrix_sync(fbl, Wl + (size_t)ni*16*WS2 + kg, WS2);
                wmma::mma_sync(acc, fah, fbh, acc);
                wmma::mma_sync(acc, fah, fbl, acc);
                wmma::mma_sync(acc, fal, fbh, acc);
            }
            __syncthreads();
            if (ci+2 < 4) load_h(ci&1, ci+2);
        }
        wmma::store_matrix_sync(Cs + khalf*2048 + ni*16*32 + mi*16, acc, 32,
                                wmma::mem_col_major);
        __syncthreads();

        float g0 = Cs[(0*16+cl_h)*32+cl_b] + Cs[2048+(0*16+cl_h)*32+cl_b] + li0;
        float g1 = Cs[(1*16+cl_h)*32+cl_b] + Cs[2048+(1*16+cl_h)*32+cl_b] + li1;
        float g2 = Cs[(2*16+cl_h)*32+cl_b] + Cs[2048+(2*16+cl_h)*32+cl_b] + li2;
        float g3 = Cs[(3*16+cl_h)*32+cl_b] + Cs[2048+(3*16+cl_h)*32+cl_b] + li3;
        float cn = sigf(g1)*c2r + sigf(g0)*tanhf(g2);
        float hn = sigf(g3)*tanhf(cn);
        c2r = cn;
        __nv_bfloat16 hhi, hlo;
        bsplit(hn, &hhi, &hlo);
        g_a2h[p^1][hg*BB + bG] = hhi;
        g_a2l[p^1][hg*BB + bG] = hlo;
        size_t yo = (size_t)t*K2TOT*BB + hg*BB + bG;
        g_yT_h[yo] = hhi;
        g_yT_l[yo] = hlo;
        if (t == TT-1){
            g_h2f[(size_t)bG*HH + hg] = hn;
            g_c2f[(size_t)bG*HH + hg] = cn;
        }
        gbar();
    }
}

// ================= parallel bf16-split wmma GEMM ==============================
__device__ __forceinline__ void wmma_gemm(
    const __nv_bfloat16* __restrict__ Ah, const __nv_bfloat16* __restrict__ Al,
    const __nv_bfloat16* __restrict__ Wh, const __nv_bfloat16* __restrict__ Wl,
    size_t wstr, int nch, char* smraw, float* Cs, wmma::layout_t clay)
{
    __nv_bfloat16* st = (__nv_bfloat16*)smraw;
    const int tid = threadIdx.x;
    const int w  = tid >> 5;
    const int wm = w & 3, wn = w >> 2;

    wmma::fragment<wmma::accumulator,16,16,16,float> acc[2][4];
    #pragma unroll
    for (int i=0;i<2;i++)
        #pragma unroll
        for (int j=0;j<4;j++) wmma::fill_fragment(acc[i][j], 0.f);

    auto load_stage = [&](int c){
        __nv_bfloat16* sb = st + (c&1)*32768;
        const __nv_bfloat16* asrc[2] = {Ah, Al};
        #pragma unroll
        for (int tA = 0; tA < 2; tA++){
            __nv_bfloat16* tb = sb + tA*8192;
            const __nv_bfloat16* bp = asrc[tA] + (size_t)(c*64)*128;
            for (int q = tid; q < 1024; q += 256){
                int kk = q >> 4, r = q & 15;
                cpa16(tb + kk*128 + r*8, bp + (size_t)kk*128 + r*8);
            }
        }
        const __nv_bfloat16* wsrc[2] = {Wh, Wl};
        #pragma unroll
        for (int tW = 0; tW < 2; tW++){
            __nv_bfloat16* tb = sb + 16384 + tW*8192;
            const __nv_bfloat16* bp = wsrc[tW] + (size_t)c*64;
            for (int q = tid; q < 1024; q += 256){
                int n = q >> 3, i = q & 7;
                cpa16(tb + n*64 + i*8, bp + (size_t)n*wstr + i*8);
            }
        }
        cpcommit();
    };

    load_stage(0);
    if (nch > 1) load_stage(1);
    else cpcommit();

    for (int c = 0; c < nch; c++){
        if (c+1 < nch) cpwait1(); else cpwait0();
        __syncthreads();
        __nv_bfloat16* sb = st + (c&1)*32768;
        __nv_bfloat16* At_h = sb;
        __nv_bfloat16* At_l = sb + 8192;
        __nv_bfloat16* Wt_h = sb + 16384;
        __nv_bfloat16* Wt_l = sb + 24576;
        #pragma unroll
        for (int ks = 0; ks < 4; ks++){
            wmma::fragment<wmma::matrix_a,16,16,16,__nv_bfloat16,wmma::col_major> ah[2], al[2];
            #pragma unroll
            for (int i=0;i<2;i++){
                wmma::load_matrix_sync(ah[i], At_h + ks*16*128 + wm*32 + i*16, 128);
                wmma::load_matrix_sync(al[i], At_l + ks*16*128 + wm*32 + i*16, 128);
            }
            #pragma unroll
            for (int j=0;j<4;j++){
                wmma::fragment<wmma::matrix_b,16,16,16,__nv_bfloat16,wmma::col_major> bh, blo;
                wmma::load_matrix_sync(bh,  Wt_h + (wn*64 + j*16)*64 + ks*16, 64);
                wmma::load_matrix_sync(blo, Wt_l + (wn*64 + j*16)*64 + ks*16, 64);
                #pragma unroll
                for (int i=0;i<2;i++){
                    wmma::mma_sync(acc[i][j], ah[i], bh,  acc[i][j]);
                    wmma::mma_sync(acc[i][j], ah[i], blo, acc[i][j]);
                    wmma::mma_sync(acc[i][j], al[i], bh,  acc[i][j]);
                }
            }
        }
        __syncthreads();
        if (c+2 < nch) load_stage(c+2);
    }

    #pragma unroll
    for (int i=0;i<2;i++)
        #pragma unroll
        for (int j=0;j<4;j++){
            int m0 = wm*32 + i*16, n0 = wn*64 + j*16;
            float* p = (clay == wmma::mem_col_major) ? Cs + n0*128 + m0
                                                     : Cs + m0*128 + n0;
            wmma::store_matrix_sync(p, acc[i][j], 128, clay);
        }
    __syncthreads();
}

// ---------------- l2in ---------------------------------------------------------
__global__ void __launch_bounds__(256,1) k_l2in_mma(const float* __restrict__ bl)
{
    extern __shared__ char smraw[];
    const int tid = threadIdx.x;
    const int t = blockIdx.y, j0 = blockIdx.x*128;
    float* Cs = (float*)smraw;

    wmma_gemm(g_featT_h + (size_t)t*K1PAD*BB, g_featT_l + (size_t)t*K1PAD*BB,
              g_wl_h + (size_t)j0*K1PAD,      g_wl_l + (size_t)j0*K1PAD,
              K1PAD, 9, smraw, Cs, wmma::mem_col_major);

    for (int idx = tid; idx < 128*128; idx += 256){
        int j = idx >> 7, b = idx & 127;
        g_l2inT[((size_t)t*G4 + j0 + j)*BB + b] = Cs[idx] + bl[j0 + j];
    }
}

// ---------------- output projection --------------------------------------------
__global__ void __launch_bounds__(256,1) k_out_mma(const float* __restrict__ b2,
                                                   float* __restrict__ out)
{
    extern __shared__ char smraw[];
    const int tid = threadIdx.x;
    const int t = blockIdx.x;
    float* Cs = (float*)smraw;

    wmma_gemm(g_yT_h + (size_t)t*K2TOT*BB, g_yT_l + (size_t)t*K2TOT*BB,
              g_wo_h, g_wo_l,
              K2TOT, 8, smraw, Cs, wmma::mem_row_major);

    for (int idx = tid; idx < 128*128; idx += 256){
        int b = idx >> 7, j = idx & 127;
        if (j < OUTD) out[((size_t)b*TT + t)*OUTD + j] = Cs[idx] + b2[j];
    }
}

// ---------------- final states -------------------------------------------------
__global__ void k_states(float* __restrict__ out, int out_size)
{
    const int base = BB*TT*OUTD;
    if (base + 4*BB*HH > out_size) return;
    int i = blockIdx.x*256 + threadIdx.x;
    if (i < BB*HH){
        out[base            + i] = g_h1f[i];
        out[base +   BB*HH  + i] = g_c1f[i];
        out[base + 2*BB*HH  + i] = g_h2f[i];
        out[base + 3*BB*HH  + i] = g_c2f[i];
    }
}

// ---------------- launch -------------------------------------------------------
extern "C" void kernel_launch(void* const* d_in, const int* in_sizes, int n_in,
                              void* d_out, int out_size)
{
    const float* x    = (const float*)d_in[0];
    const float* sent = (const float*)d_in[1];
    const float* h1h  = (const float*)d_in[2];
    const float* h1c  = (const float*)d_in[3];
    const float* h2h  = (const float*)d_in[4];
    const float* h2c  = (const float*)d_in[5];
    const float* Wihc = (const float*)d_in[6];
    const float* Whhc = (const float*)d_in[7];
    const float* bc   = (const float*)d_in[8];
    const float* Wihl = (const float*)d_in[9];
    const float* Whhl = (const float*)d_in[10];
    const float* bl   = (const float*)d_in[11];
    const float* W1   = (const float*)d_in[12];
    const float* b1   = (const float*)d_in[13];
    const float* W2   = (const float*)d_in[14];
    const float* b2   = (const float*)d_in[15];
    float* out = (float*)d_out;

    const int SMEM1 = 208256;     // W(146K) + 2x20.5K stages/Cs + attn bufs
    const int SMEM2 = 174080;     // W(130K) + 2x20.5K stages/Cs
    const int SMEMP = 2*65536;
    cudaFuncSetAttribute(k_rec1, cudaFuncAttributeMaxDynamicSharedMemorySize, SMEM1);
    cudaFuncSetAttribute(k_rec2, cudaFuncAttributeMaxDynamicSharedMemorySize, SMEM2);
    cudaFuncSetAttribute(k_l2in_mma, cudaFuncAttributeMaxDynamicSharedMemorySize, SMEMP);
    cudaFuncSetAttribute(k_out_mma, cudaFuncAttributeMaxDynamicSharedMemorySize, SMEMP);

    k_init<<<256,256>>>(h1h, h2h);
    k_cvt_w<<<512,256>>>(Wihl, W2);
    k_rec1<<<NBLK,512,SMEM1>>>(x, Wihc, Whhc, bc, W1, b1, sent, h1c);
    k_l2in_mma<<<dim3(16,TT),256,SMEMP>>>(bl);
    k_rec2<<<NBLK,512,SMEM2>>>(Whhl, h2c);
    k_out_mma<<<TT,256,SMEMP>>>(b2, out);
    k_states<<<(BB*HH+255)/256,256>>>(out, out_size);
}